// round 7
// baseline (speedup 1.0000x reference)
#include <cuda_runtime.h>
#include <cuda_bf16.h>
#include <mma.h>
#include <math.h>

using namespace nvcuda;

#define BB 64
#define SS 512
#define DD 1024
#define HH 1024
#define HPAD 68                          // floats per h^T row (pad for banks)

// Scratch (device globals — allocation-free rule)
__device__ float g_hT[2][HH * HPAD];                    // h^T [1024][68], tf32, dbl-buf
__device__ float g_xg[(size_t)SS * 4 * HH * BB];        // x @ W_in, [S][4][H][B]
__device__ unsigned g_cnt = 0;
__device__ unsigned g_gen = 0;

// ---------------------------------------------------------------------------
// Grid barrier (all blocks co-resident: 1 block/SM)
// ---------------------------------------------------------------------------
__device__ __forceinline__ void grid_sync(unsigned nb) {
    __threadfence();
    __syncthreads();
    if (threadIdx.x == 0) {
        volatile unsigned* genp = &g_gen;
        unsigned old = *genp;
        __threadfence();
        if (atomicAdd(&g_cnt, 1u) == nb - 1u) {
            g_cnt = 0u;
            __threadfence();
            *genp = old + 1u;
        } else {
            while (*genp == old) { }
        }
    }
    __syncthreads();
}

__device__ __forceinline__ float fsig(float x) {
    x = fminf(fmaxf(x, -30.f), 30.f);
    float e = __expf(-x);
    return __fdividef(1.f, 1.f + e);
}
__device__ __forceinline__ float ftanh(float x) {
    x = fminf(fmaxf(x, -15.f), 15.f);
    float e = __expf(2.f * x);
    return __fdividef(e - 1.f, e + 1.f);
}

// ---------------------------------------------------------------------------
// mbarrier + bulk-copy helpers
// ---------------------------------------------------------------------------
__device__ __forceinline__ unsigned smem_u32(const void* p) {
    return (unsigned)__cvta_generic_to_shared(p);
}
__device__ __forceinline__ void mbar_init(unsigned a, unsigned cnt) {
    asm volatile("mbarrier.init.shared.b64 [%0], %1;" :: "r"(a), "r"(cnt) : "memory");
}
__device__ __forceinline__ void mbar_expect_tx(unsigned a, unsigned bytes) {
    asm volatile("mbarrier.arrive.expect_tx.shared.b64 _, [%0], %1;"
                 :: "r"(a), "r"(bytes) : "memory");
}
__device__ __forceinline__ void mbar_wait(unsigned a, unsigned parity) {
    unsigned done;
    asm volatile(
        "{\n\t.reg .pred p;\n\t"
        "mbarrier.try_wait.parity.shared.b64 p, [%1], %2;\n\t"
        "selp.b32 %0, 1, 0, p;\n\t}"
        : "=r"(done) : "r"(a), "r"(parity) : "memory");
    if (!done) {
        asm volatile(
            "{\n\t.reg .pred P1;\n\t"
            "W_%=:\n\t"
            "mbarrier.try_wait.parity.shared.b64 P1, [%0], %1, 0x989680;\n\t"
            "@P1 bra.uni D_%=;\n\t"
            "bra.uni W_%=;\n\t"
            "D_%=:\n\t}"
            :: "r"(a), "r"(parity) : "memory");
    }
}
__device__ __forceinline__ void bulk_g2s(unsigned dst, const void* src,
                                         unsigned bytes, unsigned mbar) {
    asm volatile(
        "cp.async.bulk.shared::cluster.global.mbarrier::complete_tx::bytes "
        "[%0], [%1], %2, [%3];"
        :: "r"(dst), "l"(src), "r"(bytes), "r"(mbar) : "memory");
}

// ---------------------------------------------------------------------------
// Phase 1: xg = x @ W_in, tf32 wmma, 128x128 tile, BK=32, double-buffered.
// Output stored as [S][4][H][B] (col-major store) for phase-2 bulk reads.
// ---------------------------------------------------------------------------
__global__ void __launch_bounds__(256)
xw_gemm(const float* __restrict__ x, const float* __restrict__ Win)
{
    extern __shared__ float sm1[];
    float* As = sm1;                    // [2][128][40]
    float* Bs = sm1 + 2 * 128 * 40;     // [2][32][136]

    const int tid  = threadIdx.x;
    const int warp = tid >> 5;
    const int wm   = warp >> 2;
    const int wn   = warp & 3;
    const int row0 = blockIdx.y * 128;
    const int col0 = blockIdx.x * 128;
    const int g    = col0 >> 10;
    const int j0   = col0 & 1023;
    const int s0   = row0 >> 6;
    const float* Wg = Win + (size_t)g * (DD * HH);

    const int ac4 = tid & 7;
    const int bc4 = tid & 31;
    const int bkr = tid >> 5;

    const float* arow[4];
    int arows[4];
#pragma unroll
    for (int i = 0; i < 4; i++) {
        int q = tid + 256 * i;
        int r = q >> 3;
        arows[i] = r;
        int m = row0 + r;
        int s = m >> 6, b = m & 63;
        arow[i] = x + ((size_t)b * SS + s) * DD + ac4 * 4;
    }

    wmma::fragment<wmma::accumulator, 16, 16, 8, float> acc[4][2];
#pragma unroll
    for (int i = 0; i < 4; i++)
#pragma unroll
        for (int j = 0; j < 2; j++) wmma::fill_fragment(acc[i][j], 0.0f);

    float4 ra[4], rb[4];

#define P1_LOAD(kc_) {                                                          \
    for (int i_ = 0; i_ < 4; i_++)                                              \
        ra[i_] = *(const float4*)(arow[i_] + (kc_));                            \
    for (int i_ = 0; i_ < 4; i_++)                                              \
        rb[i_] = *(const float4*)(Wg + (size_t)((kc_) + bkr + 8 * i_) * HH      \
                                      + j0 + bc4 * 4);                          \
}

#define P1_STS(p_) {                                                            \
    for (int i_ = 0; i_ < 4; i_++) {                                            \
        float4 t_;                                                              \
        t_.x = wmma::__float_to_tf32(ra[i_].x);                                 \
        t_.y = wmma::__float_to_tf32(ra[i_].y);                                 \
        t_.z = wmma::__float_to_tf32(ra[i_].z);                                 \
        t_.w = wmma::__float_to_tf32(ra[i_].w);                                 \
        *(float4*)(As + (p_) * 5120 + arows[i_] * 40 + ac4 * 4) = t_;           \
    }                                                                           \
    for (int i_ = 0; i_ < 4; i_++) {                                            \
        float4 t_;                                                              \
        t_.x = wmma::__float_to_tf32(rb[i_].x);                                 \
        t_.y = wmma::__float_to_tf32(rb[i_].y);                                 \
        t_.z = wmma::__float_to_tf32(rb[i_].z);                                 \
        t_.w = wmma::__float_to_tf32(rb[i_].w);                                 \
        *(float4*)(Bs + (p_) * 4352 + (bkr + 8 * i_) * 136 + bc4 * 4) = t_;     \
    }                                                                           \
}

    P1_LOAD(0);
    P1_STS(0);
    __syncthreads();

    int p = 0;
    for (int it = 0; it < 32; ++it) {
        if (it < 31) { P1_LOAD((it + 1) * 32); }

        wmma::fragment<wmma::matrix_a, 16, 16, 8, wmma::precision::tf32, wmma::row_major> af[4];
        wmma::fragment<wmma::matrix_b, 16, 16, 8, wmma::precision::tf32, wmma::row_major> bf[2];
#pragma unroll
        for (int kk = 0; kk < 32; kk += 8) {
#pragma unroll
            for (int i = 0; i < 4; i++)
                wmma::load_matrix_sync(af[i], As + p * 5120 + (wm * 64 + i * 16) * 40 + kk, 40);
#pragma unroll
            for (int j = 0; j < 2; j++)
                wmma::load_matrix_sync(bf[j], Bs + p * 4352 + kk * 136 + wn * 32 + j * 16, 136);
#pragma unroll
            for (int i = 0; i < 4; i++)
#pragma unroll
                for (int j = 0; j < 2; j++)
                    wmma::mma_sync(acc[i][j], af[i], bf[j], acc[i][j]);
        }
        __syncthreads();
        if (it < 31) {
            P1_STS(p ^ 1);
            __syncthreads();
            p ^= 1;
        }
    }

    // epilogue: col-major store into [S][4][H][B]  (b fastest)
    {
        float* base = g_xg + (size_t)(s0 + wm) * (4 * HH * BB)
                           + (size_t)g * (HH * BB);
#pragma unroll
        for (int i = 0; i < 4; i++)
#pragma unroll
            for (int j = 0; j < 2; j++) {
                float* dst = base + (size_t)(j0 + wn * 32 + j * 16) * BB + i * 16;
                wmma::store_matrix_sync(dst, acc[i][j], BB, wmma::mem_col_major);
            }
    }
#undef P1_LOAD
#undef P1_STS
}

// ---------------------------------------------------------------------------
// Phase 2: persistent recurrence, h streamed via cp.async.bulk (TMA path).
// G^T[32 gate-cols][64 b] = W^T x h^T.  W resident smem [k][36] used as
// matrix_a col_major; h^T chunks [32k][68] via 4-stage mbarrier pipeline.
// 8 warps = 2 m-tiles x 4 b-tiles, each 16x16, full K.
// ---------------------------------------------------------------------------
__global__ void __launch_bounds__(256)
lstm_rec(const float* __restrict__ hin, const float* __restrict__ cin,
         const float* __restrict__ Whid, const float* __restrict__ bias,
         float* __restrict__ out)
{
    extern __shared__ float sm[];
    // layout (floats): [0:16) mbarriers (5 x u64), then:
    float* Wsm = sm + 16;                   // [1024][36]
    float* As  = Wsm + 1024 * 36;           // [4 stages][32][68]
    float* gsm = As + 4 * 32 * HPAD;        // [32 n][68] G^T
    float* xgs = gsm + 32 * HPAD;           // [32 n][68] xg slice
    float* csm = xgs + 32 * HPAD;           // [64][8] cell state
    float* bsm = csm + 512;                 // [32] bias slice

    const unsigned mb_base = smem_u32(sm);  // stage mbar i at +8*i, xg at +32
    const int tid  = threadIdx.x;
    const int warp = tid >> 5;
    const int wm2  = warp & 1;              // m-tile (gate cols 16*wm2..)
    const int wn4  = warp >> 1;             // b-tile (16*wn4..)
    const int j0   = blockIdx.x * 8;
    const unsigned NB = gridDim.x;

    const unsigned CHUNK_B = 32 * HPAD * 4; // 8704

    // one-time init
    for (int q = tid; q < 1024 * 32; q += 256) {
        int k = q >> 5, n = q & 31, gg = n >> 3, jj = n & 7;
        Wsm[k * 36 + n] =
            wmma::__float_to_tf32(Whid[((size_t)gg * HH + k) * HH + j0 + jj]);
    }
    if (tid < 32)
        bsm[tid] = bias[(tid >> 3) * HH + j0 + (tid & 7)];
    for (int idx = tid; idx < 512; idx += 256) {
        int r = idx >> 3, jj = idx & 7;
        csm[idx] = cin[r * HH + j0 + jj];
        g_hT[0][(j0 + jj) * HPAD + r] =
            wmma::__float_to_tf32(hin[r * HH + j0 + jj]);
    }
    if (tid == 0) {
#pragma unroll
        for (int i = 0; i < 5; i++) mbar_init(mb_base + 8 * i, 1);
        asm volatile("fence.proxy.async.shared::cta;" ::: "memory");
    }
    grid_sync(NB);

    const unsigned as_u32 = smem_u32(As);
    const unsigned xgs_u32 = smem_u32(xgs);

    for (int s = 0; s < SS; ++s) {
        const float* hcur = g_hT[s & 1];
        float*       hnxt = g_hT[(s & 1) ^ 1];
        const float* xgp  = g_xg + (size_t)s * (4 * HH * BB);

        // issue chunks 0..3 + xg slice (thread 0; TMA engine does the work)
        if (tid == 0) {
#pragma unroll
            for (int c = 0; c < 4; c++) {
                unsigned mb = mb_base + 8 * c;
                mbar_expect_tx(mb, CHUNK_B);
                bulk_g2s(as_u32 + c * CHUNK_B, hcur + c * (32 * HPAD), CHUNK_B, mb);
            }
            mbar_expect_tx(mb_base + 32, 32 * BB * 4);
            for (int n = 0; n < 32; n++) {
                int gg = n >> 3, jj = n & 7;
                bulk_g2s(xgs_u32 + n * HPAD * 4,
                         xgp + ((size_t)gg * HH + j0 + jj) * BB,
                         BB * 4, mb_base + 32);
            }
        }

        wmma::fragment<wmma::accumulator, 16, 16, 8, float> acc;
        wmma::fill_fragment(acc, 0.0f);

        for (int it = 0; it < 32; ++it) {
            const int cg = s * 32 + it;
            const int st = cg & 3;
            const unsigned ph = (unsigned)(cg >> 2) & 1u;
            mbar_wait(mb_base + 8 * st, ph);

            const float* abuf = As + st * (32 * HPAD);
            const int kc0 = it * 32;
            wmma::fragment<wmma::matrix_a, 16, 16, 8, wmma::precision::tf32, wmma::col_major> af;
            wmma::fragment<wmma::matrix_b, 16, 16, 8, wmma::precision::tf32, wmma::row_major> bf;
#pragma unroll
            for (int k8 = 0; k8 < 32; k8 += 8) {
                wmma::load_matrix_sync(af, Wsm + (kc0 + k8) * 36 + wm2 * 16, 36);
                wmma::load_matrix_sync(bf, abuf + k8 * HPAD + wn4 * 16, HPAD);
                wmma::mma_sync(acc, af, bf, acc);
            }
            __syncthreads();                 // stage fully consumed
            if (tid == 0 && it < 28) {
                int c = it + 4;              // goes into same stage st
                unsigned mb = mb_base + 8 * st;
                mbar_expect_tx(mb, CHUNK_B);
                bulk_g2s(as_u32 + st * CHUNK_B, hcur + c * (32 * HPAD), CHUNK_B, mb);
            }
        }

        // G^T -> gsm [n][68]
        wmma::store_matrix_sync(gsm + (wm2 * 16) * HPAD + wn4 * 16, acc, HPAD,
                                wmma::mem_row_major);
        mbar_wait(mb_base + 32, (unsigned)(s & 1));
        __syncthreads();

        // gates + state update + outputs
        for (int idx = tid; idx < 512; idx += 256) {
            int r = idx >> 3, jj = idx & 7;
            float gf = gsm[jj * HPAD + r]        + xgs[jj * HPAD + r]        + bsm[jj];
            float gi = gsm[(8 + jj) * HPAD + r]  + xgs[(8 + jj) * HPAD + r]  + bsm[8 + jj];
            float go = gsm[(16 + jj) * HPAD + r] + xgs[(16 + jj) * HPAD + r] + bsm[16 + jj];
            float ga = gsm[(24 + jj) * HPAD + r] + xgs[(24 + jj) * HPAD + r] + bsm[24 + jj];
            float f  = fsig(gf);
            float ii = fsig(gi);
            float oo = fsig(go);
            float aa = ftanh(ga);
            float cn = f * csm[idx] + ii * aa;
            float hv = ftanh(cn) * oo;
            csm[idx] = cn;
            size_t ob = ((size_t)r * SS + s) * HH + j0 + jj;
            out[ob] = hv;                               // hs [B,S,H]
            out[(size_t)BB * SS * HH + ob] = cn;        // cs [B,S,H]
            hnxt[(j0 + jj) * HPAD + r] = wmma::__float_to_tf32(hv);
        }
        grid_sync(NB);
    }
}

// ---------------------------------------------------------------------------
extern "C" void kernel_launch(void* const* d_in, const int* in_sizes, int n_in,
                              void* d_out, int out_size)
{
    const float* x    = (const float*)d_in[0];
    const float* h0   = (const float*)d_in[1];
    const float* c0   = (const float*)d_in[2];
    const float* Win  = (const float*)d_in[3];
    const float* Whid = (const float*)d_in[4];
    const float* bias = (const float*)d_in[5];
    float* out = (float*)d_out;

    const int SMEM1 = (2 * 128 * 40 + 2 * 32 * 136) * 4;                  // 75776 B
    const int SMEM2 = (16 + 1024 * 36 + 4 * 32 * HPAD + 2 * 32 * HPAD
                       + 512 + 32) * 4;                                   // 201920 B

    cudaFuncSetAttribute(xw_gemm,  cudaFuncAttributeMaxDynamicSharedMemorySize, SMEM1);
    cudaFuncSetAttribute(lstm_rec, cudaFuncAttributeMaxDynamicSharedMemorySize, SMEM2);

    // Phase 1: xg = x @ W_in  -> [S][4][H][B]
    xw_gemm<<<dim3(32, 256), 256, SMEM1>>>(x, Win);

    // Phase 2: persistent recurrence, 128 blocks (1/SM, co-resident)
    lstm_rec<<<128, 256, SMEM2>>>(h0, c0, Whid, bias, out);
}

// round 8
// speedup vs baseline: 1.1991x; 1.1991x over previous
#include <cuda_runtime.h>
#include <cuda_bf16.h>
#include <mma.h>
#include <math.h>

using namespace nvcuda;

#define BB 64
#define SS 512
#define DD 1024
#define HH 1024
#define HPAD 68                          // floats per h^T row (pad for banks)

// Scratch (device globals — allocation-free rule)
__device__ float g_hT[2][HH * HPAD];                    // h^T [1024][68], tf32, dbl-buf
__device__ float g_xg[(size_t)SS * 4 * HH * BB];        // x @ W_in, [S][4][H][B]
__device__ unsigned g_cnt = 0;
__device__ unsigned g_gen = 0;

// ---------------------------------------------------------------------------
// Grid barrier (all blocks co-resident: 1 block/SM)
// ---------------------------------------------------------------------------
__device__ __forceinline__ void grid_sync(unsigned nb) {
    __threadfence();
    __syncthreads();
    if (threadIdx.x == 0) {
        volatile unsigned* genp = &g_gen;
        unsigned old = *genp;
        __threadfence();
        if (atomicAdd(&g_cnt, 1u) == nb - 1u) {
            g_cnt = 0u;
            __threadfence();
            *genp = old + 1u;
        } else {
            while (*genp == old) { }
        }
    }
    __syncthreads();
}

__device__ __forceinline__ float fsig(float x) {
    x = fminf(fmaxf(x, -30.f), 30.f);
    float e = __expf(-x);
    return __fdividef(1.f, 1.f + e);
}
__device__ __forceinline__ float ftanh(float x) {
    x = fminf(fmaxf(x, -15.f), 15.f);
    float e = __expf(2.f * x);
    return __fdividef(e - 1.f, e + 1.f);
}

// ---------------------------------------------------------------------------
// mbarrier + bulk-copy helpers
// ---------------------------------------------------------------------------
__device__ __forceinline__ unsigned smem_u32(const void* p) {
    return (unsigned)__cvta_generic_to_shared(p);
}
__device__ __forceinline__ void mbar_init(unsigned a, unsigned cnt) {
    asm volatile("mbarrier.init.shared.b64 [%0], %1;" :: "r"(a), "r"(cnt) : "memory");
}
__device__ __forceinline__ void mbar_expect_tx(unsigned a, unsigned bytes) {
    asm volatile("mbarrier.arrive.expect_tx.shared.b64 _, [%0], %1;"
                 :: "r"(a), "r"(bytes) : "memory");
}
__device__ __forceinline__ void mbar_wait(unsigned a, unsigned parity) {
    unsigned done;
    asm volatile(
        "{\n\t.reg .pred p;\n\t"
        "mbarrier.try_wait.parity.shared.b64 p, [%1], %2;\n\t"
        "selp.b32 %0, 1, 0, p;\n\t}"
        : "=r"(done) : "r"(a), "r"(parity) : "memory");
    if (!done) {
        asm volatile(
            "{\n\t.reg .pred P1;\n\t"
            "W_%=:\n\t"
            "mbarrier.try_wait.parity.shared.b64 P1, [%0], %1, 0x989680;\n\t"
            "@P1 bra.uni D_%=;\n\t"
            "bra.uni W_%=;\n\t"
            "D_%=:\n\t}"
            :: "r"(a), "r"(parity) : "memory");
    }
}
__device__ __forceinline__ void bulk_g2s(unsigned dst, const void* src,
                                         unsigned bytes, unsigned mbar) {
    asm volatile(
        "cp.async.bulk.shared::cluster.global.mbarrier::complete_tx::bytes "
        "[%0], [%1], %2, [%3];"
        :: "r"(dst), "l"(src), "r"(bytes), "r"(mbar) : "memory");
}

// ---------------------------------------------------------------------------
// Phase 1: xg = x @ W_in, tf32 wmma, 128x128 tile, BK=32, double-buffered.
// Output stored as [S][4][H][B] (col-major store) for phase-2 reads.
// ---------------------------------------------------------------------------
__global__ void __launch_bounds__(256)
xw_gemm(const float* __restrict__ x, const float* __restrict__ Win)
{
    extern __shared__ float sm1[];
    float* As = sm1;                    // [2][128][40]
    float* Bs = sm1 + 2 * 128 * 40;     // [2][32][136]

    const int tid  = threadIdx.x;
    const int warp = tid >> 5;
    const int wm   = warp >> 2;
    const int wn   = warp & 3;
    const int row0 = blockIdx.y * 128;
    const int col0 = blockIdx.x * 128;
    const int g    = col0 >> 10;
    const int j0   = col0 & 1023;
    const int s0   = row0 >> 6;
    const float* Wg = Win + (size_t)g * (DD * HH);

    const int ac4 = tid & 7;
    const int bc4 = tid & 31;
    const int bkr = tid >> 5;

    const float* arow[4];
    int arows[4];
#pragma unroll
    for (int i = 0; i < 4; i++) {
        int q = tid + 256 * i;
        int r = q >> 3;
        arows[i] = r;
        int m = row0 + r;
        int s = m >> 6, b = m & 63;
        arow[i] = x + ((size_t)b * SS + s) * DD + ac4 * 4;
    }

    wmma::fragment<wmma::accumulator, 16, 16, 8, float> acc[4][2];
#pragma unroll
    for (int i = 0; i < 4; i++)
#pragma unroll
        for (int j = 0; j < 2; j++) wmma::fill_fragment(acc[i][j], 0.0f);

    float4 ra[4], rb[4];

#define P1_LOAD(kc_) {                                                          \
    for (int i_ = 0; i_ < 4; i_++)                                              \
        ra[i_] = *(const float4*)(arow[i_] + (kc_));                            \
    for (int i_ = 0; i_ < 4; i_++)                                              \
        rb[i_] = *(const float4*)(Wg + (size_t)((kc_) + bkr + 8 * i_) * HH      \
                                      + j0 + bc4 * 4);                          \
}

#define P1_STS(p_) {                                                            \
    for (int i_ = 0; i_ < 4; i_++) {                                            \
        float4 t_;                                                              \
        t_.x = wmma::__float_to_tf32(ra[i_].x);                                 \
        t_.y = wmma::__float_to_tf32(ra[i_].y);                                 \
        t_.z = wmma::__float_to_tf32(ra[i_].z);                                 \
        t_.w = wmma::__float_to_tf32(ra[i_].w);                                 \
        *(float4*)(As + (p_) * 5120 + arows[i_] * 40 + ac4 * 4) = t_;           \
    }                                                                           \
    for (int i_ = 0; i_ < 4; i_++) {                                            \
        float4 t_;                                                              \
        t_.x = wmma::__float_to_tf32(rb[i_].x);                                 \
        t_.y = wmma::__float_to_tf32(rb[i_].y);                                 \
        t_.z = wmma::__float_to_tf32(rb[i_].z);                                 \
        t_.w = wmma::__float_to_tf32(rb[i_].w);                                 \
        *(float4*)(Bs + (p_) * 4352 + (bkr + 8 * i_) * 136 + bc4 * 4) = t_;     \
    }                                                                           \
}

    P1_LOAD(0);
    P1_STS(0);
    __syncthreads();

    int p = 0;
    for (int it = 0; it < 32; ++it) {
        if (it < 31) { P1_LOAD((it + 1) * 32); }

        wmma::fragment<wmma::matrix_a, 16, 16, 8, wmma::precision::tf32, wmma::row_major> af[4];
        wmma::fragment<wmma::matrix_b, 16, 16, 8, wmma::precision::tf32, wmma::row_major> bf[2];
#pragma unroll
        for (int kk = 0; kk < 32; kk += 8) {
#pragma unroll
            for (int i = 0; i < 4; i++)
                wmma::load_matrix_sync(af[i], As + p * 5120 + (wm * 64 + i * 16) * 40 + kk, 40);
#pragma unroll
            for (int j = 0; j < 2; j++)
                wmma::load_matrix_sync(bf[j], Bs + p * 4352 + kk * 136 + wn * 32 + j * 16, 136);
#pragma unroll
            for (int i = 0; i < 4; i++)
#pragma unroll
                for (int j = 0; j < 2; j++)
                    wmma::mma_sync(acc[i][j], af[i], bf[j], acc[i][j]);
        }
        __syncthreads();
        if (it < 31) {
            P1_STS(p ^ 1);
            __syncthreads();
            p ^= 1;
        }
    }

    // epilogue: col-major store into [S][4][H][B]  (b fastest)
    {
        float* base = g_xg + (size_t)(s0 + wm) * (4 * HH * BB)
                           + (size_t)g * (HH * BB);
#pragma unroll
        for (int i = 0; i < 4; i++)
#pragma unroll
            for (int j = 0; j < 2; j++) {
                float* dst = base + (size_t)(j0 + wn * 32 + j * 16) * BB + i * 16;
                wmma::store_matrix_sync(dst, acc[i][j], BB, wmma::mem_col_major);
            }
    }
#undef P1_LOAD
#undef P1_STS
}

// ---------------------------------------------------------------------------
// Phase 2: persistent recurrence. h streamed via 8 coarse TMA bulk copies
// (128 k-rows = 34.8KB each) through 2 smem stages. xg slice prefetched to
// registers. G^T[32 n][64 b] = W^T x h^T; 8 warps = 2 n-tiles x 4 b-tiles.
// ---------------------------------------------------------------------------
__global__ void __launch_bounds__(256)
lstm_rec(const float* __restrict__ hin, const float* __restrict__ cin,
         const float* __restrict__ Whid, const float* __restrict__ bias,
         float* __restrict__ out)
{
    extern __shared__ float sm[];
    // layout (floats): [0:16) mbarriers (2 x u64 + pad), then:
    float* Wsm = sm + 16;                   // [1024][36]
    float* As  = Wsm + 1024 * 36;           // [2 stages][128][68]
    float* gsm = As + 2 * 128 * HPAD;       // [32 n][68] G^T
    float* csm = gsm + 32 * HPAD;           // [64][8] cell state
    float* bsm = csm + 512;                 // [32] bias slice

    const unsigned mb_base = smem_u32(sm);  // stage mbar i at +8*i
    const int tid  = threadIdx.x;
    const int warp = tid >> 5;
    const int wm2  = warp & 1;              // n-tile (gate cols 16*wm2..)
    const int wn4  = warp >> 1;             // b-tile (16*wn4..)
    const int j0   = blockIdx.x * 8;
    const unsigned NB = gridDim.x;

    const unsigned CHUNK_B = 128 * HPAD * 4;    // 34816 B

    // one-time init
    for (int q = tid; q < 1024 * 32; q += 256) {
        int k = q >> 5, n = q & 31, gg = n >> 3, jj = n & 7;
        Wsm[k * 36 + n] =
            wmma::__float_to_tf32(Whid[((size_t)gg * HH + k) * HH + j0 + jj]);
    }
    if (tid < 32)
        bsm[tid] = bias[(tid >> 3) * HH + j0 + (tid & 7)];
    for (int idx = tid; idx < 512; idx += 256) {
        int r = idx >> 3, jj = idx & 7;
        csm[idx] = cin[r * HH + j0 + jj];
        g_hT[0][(j0 + jj) * HPAD + r] =
            wmma::__float_to_tf32(hin[r * HH + j0 + jj]);
    }
    if (tid == 0) {
        mbar_init(mb_base + 0, 1);
        mbar_init(mb_base + 8, 1);
        asm volatile("fence.proxy.async.shared::cta;" ::: "memory");
    }
    grid_sync(NB);

    const unsigned as_u32 = smem_u32(As);

    for (int s = 0; s < SS; ++s) {
        const float* hcur = g_hT[s & 1];
        float*       hnxt = g_hT[(s & 1) ^ 1];
        const float* xgp  = g_xg + (size_t)s * (4 * HH * BB);

        // xg slice -> registers (latency hidden by the whole step)
        float xv[8];
#pragma unroll
        for (int i = 0; i < 2; i++) {
            int idx = tid + 256 * i;
            int r = idx >> 3, jj = idx & 7;
#pragma unroll
            for (int gg = 0; gg < 4; gg++)
                xv[i * 4 + gg] =
                    __ldg(xgp + (size_t)gg * (HH * BB) + (j0 + jj) * BB + r);
        }

        // issue chunks 0,1 into stages 0,1
        if (tid == 0) {
#pragma unroll
            for (int c = 0; c < 2; c++) {
                unsigned mb = mb_base + 8 * c;
                mbar_expect_tx(mb, CHUNK_B);
                bulk_g2s(as_u32 + c * CHUNK_B, hcur + c * (128 * HPAD), CHUNK_B, mb);
            }
        }

        wmma::fragment<wmma::accumulator, 16, 16, 8, float> acc0, acc1;
        wmma::fill_fragment(acc0, 0.0f);
        wmma::fill_fragment(acc1, 0.0f);

        for (int c = 0; c < 8; ++c) {
            const int cg = s * 8 + c;
            const int st = cg & 1;
            const unsigned ph = (unsigned)(cg >> 1) & 1u;
            mbar_wait(mb_base + 8 * st, ph);

            const float* abuf = As + st * (128 * HPAD);
            const int kc0 = c * 128;
            wmma::fragment<wmma::matrix_a, 16, 16, 8, wmma::precision::tf32, wmma::col_major> af;
            wmma::fragment<wmma::matrix_b, 16, 16, 8, wmma::precision::tf32, wmma::row_major> bf;
#pragma unroll
            for (int k8 = 0; k8 < 16; ++k8) {
                wmma::load_matrix_sync(af, Wsm + (kc0 + k8 * 8) * 36 + wm2 * 16, 36);
                wmma::load_matrix_sync(bf, abuf + (k8 * 8) * HPAD + wn4 * 16, HPAD);
                if (k8 & 1) wmma::mma_sync(acc1, af, bf, acc1);
                else        wmma::mma_sync(acc0, af, bf, acc0);
            }
            __syncthreads();                 // stage fully consumed
            if (tid == 0 && c < 6) {
                unsigned mb = mb_base + 8 * st;
                mbar_expect_tx(mb, CHUNK_B);
                bulk_g2s(as_u32 + st * CHUNK_B,
                         hcur + (c + 2) * (128 * HPAD), CHUNK_B, mb);
            }
        }

        // combine dual chains, G^T -> gsm [n][68]
#pragma unroll
        for (int e = 0; e < acc0.num_elements; e++) acc0.x[e] += acc1.x[e];
        wmma::store_matrix_sync(gsm + (wm2 * 16) * HPAD + wn4 * 16, acc0, HPAD,
                                wmma::mem_row_major);
        __syncthreads();

        // gates + state update + outputs
#pragma unroll
        for (int i = 0; i < 2; i++) {
            int idx = tid + 256 * i;
            int r = idx >> 3, jj = idx & 7;
            float gf = gsm[jj * HPAD + r]        + xv[i * 4 + 0] + bsm[jj];
            float gi = gsm[(8 + jj) * HPAD + r]  + xv[i * 4 + 1] + bsm[8 + jj];
            float go = gsm[(16 + jj) * HPAD + r] + xv[i * 4 + 2] + bsm[16 + jj];
            float ga = gsm[(24 + jj) * HPAD + r] + xv[i * 4 + 3] + bsm[24 + jj];
            float f  = fsig(gf);
            float ii = fsig(gi);
            float oo = fsig(go);
            float aa = ftanh(ga);
            float cn = f * csm[idx] + ii * aa;
            float hv = ftanh(cn) * oo;
            csm[idx] = cn;
            size_t ob = ((size_t)r * SS + s) * HH + j0 + jj;
            out[ob] = hv;                               // hs [B,S,H]
            out[(size_t)BB * SS * HH + ob] = cn;        // cs [B,S,H]
            hnxt[(j0 + jj) * HPAD + r] = wmma::__float_to_tf32(hv);
        }
        grid_sync(NB);
    }
}

// ---------------------------------------------------------------------------
extern "C" void kernel_launch(void* const* d_in, const int* in_sizes, int n_in,
                              void* d_out, int out_size)
{
    const float* x    = (const float*)d_in[0];
    const float* h0   = (const float*)d_in[1];
    const float* c0   = (const float*)d_in[2];
    const float* Win  = (const float*)d_in[3];
    const float* Whid = (const float*)d_in[4];
    const float* bias = (const float*)d_in[5];
    float* out = (float*)d_out;

    const int SMEM1 = (2 * 128 * 40 + 2 * 32 * 136) * 4;                  // 75776 B
    const int SMEM2 = (16 + 1024 * 36 + 2 * 128 * HPAD + 32 * HPAD
                       + 512 + 32) * 4;                                   // 228032 B

    cudaFuncSetAttribute(xw_gemm,  cudaFuncAttributeMaxDynamicSharedMemorySize, SMEM1);
    cudaFuncSetAttribute(lstm_rec, cudaFuncAttributeMaxDynamicSharedMemorySize, SMEM2);

    // Phase 1: xg = x @ W_in  -> [S][4][H][B]
    xw_gemm<<<dim3(32, 256), 256, SMEM1>>>(x, Win);

    // Phase 2: persistent recurrence, 128 blocks (1/SM, co-resident)
    lstm_rec<<<128, 256, SMEM2>>>(h0, c0, Whid, bias, out);
}

// round 9
// speedup vs baseline: 1.3255x; 1.1054x over previous
#include <cuda_runtime.h>
#include <cuda_bf16.h>
#include <mma.h>
#include <math.h>

using namespace nvcuda;

#define BB 64
#define SS 512
#define DD 1024
#define HH 1024
#define HPAD 68                          // floats per h^T row (pad for banks)
#define NCH 16                           // chunks per step
#define CROWS 64                         // k-rows per chunk
#define STG_F (CROWS * HPAD)             // 4352 floats per stage
#define CHUNK_B (STG_F * 4)              // 17408 bytes

// Scratch (device globals — allocation-free rule)
__device__ float g_hT[2][HH * HPAD];                    // h^T [1024][68], tf32, dbl-buf
__device__ float g_xg[(size_t)SS * 4 * HH * BB];        // x @ W_in, [S][4][H][B]
__device__ unsigned g_flag[NCH * 32];                   // per-chunk monotone counters

__device__ __forceinline__ float fsig(float x) {
    x = fminf(fmaxf(x, -30.f), 30.f);
    float e = __expf(-x);
    return __fdividef(1.f, 1.f + e);
}
__device__ __forceinline__ float ftanh(float x) {
    x = fminf(fmaxf(x, -15.f), 15.f);
    float e = __expf(2.f * x);
    return __fdividef(e - 1.f, e + 1.f);
}

// ---------------------------------------------------------------------------
// mbarrier + bulk-copy helpers
// ---------------------------------------------------------------------------
__device__ __forceinline__ unsigned smem_u32(const void* p) {
    return (unsigned)__cvta_generic_to_shared(p);
}
__device__ __forceinline__ void mbar_init(unsigned a, unsigned cnt) {
    asm volatile("mbarrier.init.shared.b64 [%0], %1;" :: "r"(a), "r"(cnt) : "memory");
}
__device__ __forceinline__ void mbar_expect_tx(unsigned a, unsigned bytes) {
    asm volatile("mbarrier.arrive.expect_tx.shared.b64 _, [%0], %1;"
                 :: "r"(a), "r"(bytes) : "memory");
}
__device__ __forceinline__ void mbar_arrive(unsigned a) {
    asm volatile("mbarrier.arrive.shared.b64 _, [%0];" :: "r"(a) : "memory");
}
__device__ __forceinline__ void mbar_wait(unsigned a, unsigned parity) {
    unsigned done;
    asm volatile(
        "{\n\t.reg .pred p;\n\t"
        "mbarrier.try_wait.parity.shared.b64 p, [%1], %2;\n\t"
        "selp.b32 %0, 1, 0, p;\n\t}"
        : "=r"(done) : "r"(a), "r"(parity) : "memory");
    if (!done) {
        asm volatile(
            "{\n\t.reg .pred P1;\n\t"
            "W_%=:\n\t"
            "mbarrier.try_wait.parity.shared.b64 P1, [%0], %1, 0x989680;\n\t"
            "@P1 bra.uni D_%=;\n\t"
            "bra.uni W_%=;\n\t"
            "D_%=:\n\t}"
            :: "r"(a), "r"(parity) : "memory");
    }
}
__device__ __forceinline__ void bulk_g2s(unsigned dst, const void* src,
                                         unsigned bytes, unsigned mbar) {
    asm volatile(
        "cp.async.bulk.shared::cluster.global.mbarrier::complete_tx::bytes "
        "[%0], [%1], %2, [%3];"
        :: "r"(dst), "l"(src), "r"(bytes), "r"(mbar) : "memory");
}

// ---------------------------------------------------------------------------
__global__ void reset_flags() {
    if (threadIdx.x < NCH * 32) g_flag[threadIdx.x] = 0u;
}

// ---------------------------------------------------------------------------
// Phase 1: xg = x @ W_in, tf32 wmma, 128x128 tile, BK=32, double-buffered.
// Output stored as [S][4][H][B] (col-major store) for phase-2 reads.
// ---------------------------------------------------------------------------
__global__ void __launch_bounds__(256)
xw_gemm(const float* __restrict__ x, const float* __restrict__ Win)
{
    extern __shared__ float sm1[];
    float* As = sm1;                    // [2][128][40]
    float* Bs = sm1 + 2 * 128 * 40;     // [2][32][136]

    const int tid  = threadIdx.x;
    const int warp = tid >> 5;
    const int wm   = warp >> 2;
    const int wn   = warp & 3;
    const int row0 = blockIdx.y * 128;
    const int col0 = blockIdx.x * 128;
    const int g    = col0 >> 10;
    const int j0   = col0 & 1023;
    const int s0   = row0 >> 6;
    const float* Wg = Win + (size_t)g * (DD * HH);

    const int ac4 = tid & 7;
    const int bc4 = tid & 31;
    const int bkr = tid >> 5;

    const float* arow[4];
    int arows[4];
#pragma unroll
    for (int i = 0; i < 4; i++) {
        int q = tid + 256 * i;
        int r = q >> 3;
        arows[i] = r;
        int m = row0 + r;
        int s = m >> 6, b = m & 63;
        arow[i] = x + ((size_t)b * SS + s) * DD + ac4 * 4;
    }

    wmma::fragment<wmma::accumulator, 16, 16, 8, float> acc[4][2];
#pragma unroll
    for (int i = 0; i < 4; i++)
#pragma unroll
        for (int j = 0; j < 2; j++) wmma::fill_fragment(acc[i][j], 0.0f);

    float4 ra[4], rb[4];

#define P1_LOAD(kc_) {                                                          \
    for (int i_ = 0; i_ < 4; i_++)                                              \
        ra[i_] = *(const float4*)(arow[i_] + (kc_));                            \
    for (int i_ = 0; i_ < 4; i_++)                                              \
        rb[i_] = *(const float4*)(Wg + (size_t)((kc_) + bkr + 8 * i_) * HH      \
                                      + j0 + bc4 * 4);                          \
}

#define P1_STS(p_) {                                                            \
    for (int i_ = 0; i_ < 4; i_++) {                                            \
        float4 t_;                                                              \
        t_.x = wmma::__float_to_tf32(ra[i_].x);                                 \
        t_.y = wmma::__float_to_tf32(ra[i_].y);                                 \
        t_.z = wmma::__float_to_tf32(ra[i_].z);                                 \
        t_.w = wmma::__float_to_tf32(ra[i_].w);                                 \
        *(float4*)(As + (p_) * 5120 + arows[i_] * 40 + ac4 * 4) = t_;           \
    }                                                                           \
    for (int i_ = 0; i_ < 4; i_++) {                                            \
        float4 t_;                                                              \
        t_.x = wmma::__float_to_tf32(rb[i_].x);                                 \
        t_.y = wmma::__float_to_tf32(rb[i_].y);                                 \
        t_.z = wmma::__float_to_tf32(rb[i_].z);                                 \
        t_.w = wmma::__float_to_tf32(rb[i_].w);                                 \
        *(float4*)(Bs + (p_) * 4352 + (bkr + 8 * i_) * 136 + bc4 * 4) = t_;     \
    }                                                                           \
}

    P1_LOAD(0);
    P1_STS(0);
    __syncthreads();

    int p = 0;
    for (int it = 0; it < 32; ++it) {
        if (it < 31) { P1_LOAD((it + 1) * 32); }

        wmma::fragment<wmma::matrix_a, 16, 16, 8, wmma::precision::tf32, wmma::row_major> af[4];
        wmma::fragment<wmma::matrix_b, 16, 16, 8, wmma::precision::tf32, wmma::row_major> bf[2];
#pragma unroll
        for (int kk = 0; kk < 32; kk += 8) {
#pragma unroll
            for (int i = 0; i < 4; i++)
                wmma::load_matrix_sync(af[i], As + p * 5120 + (wm * 64 + i * 16) * 40 + kk, 40);
#pragma unroll
            for (int j = 0; j < 2; j++)
                wmma::load_matrix_sync(bf[j], Bs + p * 4352 + kk * 136 + wn * 32 + j * 16, 136);
#pragma unroll
            for (int i = 0; i < 4; i++)
#pragma unroll
                for (int j = 0; j < 2; j++)
                    wmma::mma_sync(acc[i][j], af[i], bf[j], acc[i][j]);
        }
        __syncthreads();
        if (it < 31) {
            P1_STS(p ^ 1);
            __syncthreads();
            p ^= 1;
        }
    }

    // epilogue: col-major store into [S][4][H][B]  (b fastest)
    {
        float* base = g_xg + (size_t)(s0 + wm) * (4 * HH * BB)
                           + (size_t)g * (HH * BB);
#pragma unroll
        for (int i = 0; i < 4; i++)
#pragma unroll
            for (int j = 0; j < 2; j++) {
                float* dst = base + (size_t)(j0 + wn * 32 + j * 16) * BB + i * 16;
                wmma::store_matrix_sync(dst, acc[i][j], BB, wmma::mem_col_major);
            }
    }
#undef P1_LOAD
#undef P1_STS
}

// ---------------------------------------------------------------------------
// Phase 2: persistent recurrence, dataflow-synchronized (no grid barrier).
// 128 blocks x 8 h-cols. 544 threads: warps 0-15 GEMM (2-way k-split inside
// each 64-row chunk), warp 16 = producer (flag poll + TMA into 3-stage ring).
// Per-chunk flags: chunk c (h cols 64c..64c+63) produced by blocks 8c..8c+7.
// ---------------------------------------------------------------------------
__global__ void __launch_bounds__(544)
lstm_rec(const float* __restrict__ hin, const float* __restrict__ cin,
         const float* __restrict__ Whid, const float* __restrict__ bias,
         float* __restrict__ out)
{
    extern __shared__ float sm[];
    // bytes [0:24) full mbars, [24:48) empty mbars, pad to 64B
    float* Wsm  = sm + 16;                  // [1024][36]
    float* As   = Wsm + 1024 * 36;          // [3 stages][64][68]
    float* gsm  = As + 3 * STG_F;           // [32 n][68] partial (group 0)
    float* gsm2 = gsm + 32 * HPAD;          // [32 n][68] partial (group 1)
    float* csm  = gsm2 + 32 * HPAD;         // [64][8] cell state
    float* bsm  = csm + 512;                // [32] bias slice

    const unsigned mb   = smem_u32(sm);     // full[i]=mb+8i, empty[i]=mb+24+8i
    const int tid  = threadIdx.x;
    const int warp = tid >> 5;
    const int lane = tid & 31;
    const int grp  = warp >> 3;             // k-split group (0/1), warps 0-15
    const int ww   = warp & 7;
    const int wm2  = ww & 1;                // n-tile (gate cols 16*wm2..)
    const int wn4  = ww >> 1;               // b-tile (16*wn4..)
    const int j0   = blockIdx.x * 8;
    const int myflag = (blockIdx.x >> 3) * 32;   // this block's chunk counter

    // one-time init
    for (int q = tid; q < 1024 * 32; q += 544) {
        int k = q >> 5, n = q & 31, gg = n >> 3, jj = n & 7;
        Wsm[k * 36 + n] =
            wmma::__float_to_tf32(Whid[((size_t)gg * HH + k) * HH + j0 + jj]);
    }
    if (tid < 32)
        bsm[tid] = bias[(tid >> 3) * HH + j0 + (tid & 7)];
    if (tid < 512) {
        int r = tid >> 3, jj = tid & 7;
        csm[tid] = cin[r * HH + j0 + jj];
        g_hT[0][(j0 + jj) * HPAD + r] =
            wmma::__float_to_tf32(hin[r * HH + j0 + jj]);
    }
    if (tid == 0) {
#pragma unroll
        for (int i = 0; i < 3; i++) {
            mbar_init(mb + 8 * i, 1);        // full: TMA expect_tx
            mbar_init(mb + 24 + 8 * i, 16);  // empty: 16 GEMM warps
        }
        asm volatile("fence.proxy.async.shared::cta;" ::: "memory");
    }
    __threadfence();
    __syncthreads();
    if (tid == 0) atomicAdd(&g_flag[myflag], 1u);   // publish h(0)

    const unsigned as_u32 = smem_u32(As);

    // ring cursors (continuous across all steps)
    int stC = 0; unsigned phC = 0;          // consumer (full)
    int stP = 0; unsigned phP = 1;          // producer (empty)

    for (int s = 0; s < SS; ++s) {
        const float* hcur = g_hT[s & 1];
        float*       hnxt = g_hT[(s & 1) ^ 1];
        const float* xgp  = g_xg + (size_t)s * (4 * HH * BB);

        if (warp < 16) {
            // xg -> registers (independent of h; latency hidden by GEMM)
            float xv[4];
            int r = 0, jj = 0;
            if (tid < 512) {
                r = tid >> 3; jj = tid & 7;
#pragma unroll
                for (int gg = 0; gg < 4; gg++)
                    xv[gg] = __ldg(xgp + (size_t)gg * (HH * BB)
                                       + (j0 + jj) * BB + r);
            }

            wmma::fragment<wmma::accumulator, 16, 16, 8, float> acc0, acc1;
            wmma::fill_fragment(acc0, 0.0f);
            wmma::fill_fragment(acc1, 0.0f);

            for (int c = 0; c < NCH; ++c) {
                mbar_wait(mb + 8 * stC, phC);

                const float* abuf = As + stC * STG_F + (grp * 32) * HPAD;
                const int kc0 = c * CROWS + grp * 32;
                wmma::fragment<wmma::matrix_a, 16, 16, 8, wmma::precision::tf32, wmma::col_major> af;
                wmma::fragment<wmma::matrix_b, 16, 16, 8, wmma::precision::tf32, wmma::row_major> bf;
#pragma unroll
                for (int k8 = 0; k8 < 4; ++k8) {
                    wmma::load_matrix_sync(af, Wsm + (kc0 + k8 * 8) * 36 + wm2 * 16, 36);
                    wmma::load_matrix_sync(bf, abuf + (k8 * 8) * HPAD + wn4 * 16, HPAD);
                    if (k8 & 1) wmma::mma_sync(acc1, af, bf, acc1);
                    else        wmma::mma_sync(acc0, af, bf, acc0);
                }
                if (lane == 0) mbar_arrive(mb + 24 + 8 * stC);
                if (++stC == 3) { stC = 0; phC ^= 1; }
            }

#pragma unroll
            for (int e = 0; e < acc0.num_elements; e++) acc0.x[e] += acc1.x[e];
            float* gdst = (grp == 0) ? gsm : gsm2;
            wmma::store_matrix_sync(gdst + (wm2 * 16) * HPAD + wn4 * 16, acc0,
                                    HPAD, wmma::mem_row_major);
            __syncthreads();

            // gates + state update + outputs (512 threads, 1 elem each)
            if (tid < 512) {
                float gf = gsm[jj * HPAD + r]        + gsm2[jj * HPAD + r]        + xv[0] + bsm[jj];
                float gi = gsm[(8 + jj) * HPAD + r]  + gsm2[(8 + jj) * HPAD + r]  + xv[1] + bsm[8 + jj];
                float go = gsm[(16 + jj) * HPAD + r] + gsm2[(16 + jj) * HPAD + r] + xv[2] + bsm[16 + jj];
                float ga = gsm[(24 + jj) * HPAD + r] + gsm2[(24 + jj) * HPAD + r] + xv[3] + bsm[24 + jj];
                float f  = fsig(gf);
                float ii = fsig(gi);
                float oo = fsig(go);
                float aa = ftanh(ga);
                float cn = f * csm[tid] + ii * aa;
                float hv = ftanh(cn) * oo;
                csm[tid] = cn;
                size_t ob = ((size_t)r * SS + s) * HH + j0 + jj;
                out[ob] = hv;                               // hs [B,S,H]
                out[(size_t)BB * SS * HH + ob] = cn;        // cs [B,S,H]
                hnxt[(j0 + jj) * HPAD + r] = wmma::__float_to_tf32(hv);
            }
            __threadfence();
        } else {
            // producer warp: poll flags, stream 16 chunks through the ring
            if (lane == 0) {
                const unsigned tgt = 8u * (unsigned)(s + 1);
                for (int c = 0; c < NCH; ++c) {
                    mbar_wait(mb + 24 + 8 * stP, phP);       // stage free
                    volatile unsigned* f = &g_flag[c * 32];
                    while (*f < tgt) { }
                    mbar_expect_tx(mb + 8 * stP, CHUNK_B);
                    bulk_g2s(as_u32 + stP * CHUNK_B,
                             hcur + c * STG_F, CHUNK_B, mb + 8 * stP);
                    if (++stP == 3) { stP = 0; phP ^= 1; }
                }
            } else {
                // keep cursors consistent (unused lanes)
                for (int c = 0; c < NCH; ++c)
                    if (++stP == 3) { stP = 0; phP ^= 1; }
            }
            __syncthreads();    // pairs with GEMM warps' post-store barrier
        }

        __syncthreads();        // all 17 warps: h published in smem->global
        if (tid == 0) atomicAdd(&g_flag[myflag], 1u);
    }
}

// ---------------------------------------------------------------------------
extern "C" void kernel_launch(void* const* d_in, const int* in_sizes, int n_in,
                              void* d_out, int out_size)
{
    const float* x    = (const float*)d_in[0];
    const float* h0   = (const float*)d_in[1];
    const float* c0   = (const float*)d_in[2];
    const float* Win  = (const float*)d_in[3];
    const float* Whid = (const float*)d_in[4];
    const float* bias = (const float*)d_in[5];
    float* out = (float*)d_out;

    const int SMEM1 = (2 * 128 * 40 + 2 * 32 * 136) * 4;                  // 75776 B
    const int SMEM2 = (16 + 1024 * 36 + 3 * STG_F + 2 * 32 * HPAD
                       + 512 + 32) * 4;                                   // 219328 B

    cudaFuncSetAttribute(xw_gemm,  cudaFuncAttributeMaxDynamicSharedMemorySize, SMEM1);
    cudaFuncSetAttribute(lstm_rec, cudaFuncAttributeMaxDynamicSharedMemorySize, SMEM2);

    // reset dataflow counters (graph-replay safe)
    reset_flags<<<1, 512>>>();

    // Phase 1: xg = x @ W_in  -> [S][4][H][B]
    xw_gemm<<<dim3(32, 256), 256, SMEM1>>>(x, Win);

    // Phase 2: persistent recurrence, 128 blocks (1/SM, co-resident)
    lstm_rec<<<128, 544, SMEM2>>>(h0, c0, Whid, bias, out);
}